// round 8
// baseline (speedup 1.0000x reference)
#include <cuda_runtime.h>
#include <math.h>

#define NG     320
#define NS1    (NG*NG)
#define NSHOT  2
#define NSRC   8
#define NREC   96
#define NT     160
#define PML_W  20
#define NBLK   256          // 128 tiles x 2 shots
#define TPB    400
#define TILE_R 20
#define TILE_C 40
#define TCB    8            // tile-grid cols
#define TRB    16           // tile-grid rows
#define SSP    53           // stress SMEM row stride (52 used + pad)
#define SVP    49           // velocity SMEM row stride (48 used + pad)
#define IDHF   0.25f
#define DTF    4.0e-4f

// Triple-buffered global stress (only core cells written; halo source for neighbors)
__device__ float g_syy[3][NSHOT*NS1];
__device__ float g_sxy[3][NSHOT*NS1];
__device__ float g_sxx[3][NSHOT*NS1];
__device__ float g_recs[NT*NSHOT*NREC];

__device__ __align__(128) unsigned g_flag[NBLK*32];   // one line per block
__device__ __align__(128) unsigned g_count = 0;
__device__ __align__(128) volatile unsigned g_phase = 0;

__device__ __forceinline__ void gbar(unsigned target)
{
    __syncthreads();
    if (threadIdx.x == 0) {
        __threadfence();
        if (atomicAdd(&g_count, 1u) == NBLK - 1) {
            g_count = 0;
            __threadfence();
            g_phase = target;
        } else {
            while ((int)(g_phase - target) < 0) { }
        }
        __threadfence();
    }
    __syncthreads();
}

__device__ __forceinline__ unsigned ld_acq(const unsigned* p)
{
    unsigned v;
    asm volatile("ld.acquire.gpu.global.u32 %0, [%1];" : "=r"(v) : "l"(p) : "memory");
    return v;
}
__device__ __forceinline__ void red_add(unsigned* p)
{
    asm volatile("red.global.add.u32 [%0], %1;" :: "l"(p), "r"(1u) : "memory");
}

__device__ __forceinline__ float pml_b(int i)
{
    const double d0 = 3.0 * 1600.0 * log(1000.0) / (2.0 * PML_W * 4.0);
    double dd = 0.0;
    if (i < PML_W) {
        double a = (double)(PML_W - i) / PML_W;
        dd = d0 * a * a;
    } else if (i >= NG - PML_W) {
        double a = ((double)i - (NG - 1 - PML_W)) / PML_W;
        dd = d0 * a * a;
    }
    return (float)exp(-dd * 4.0e-4);
}

__device__ __forceinline__ void st2(float* __restrict__ p, int idx, float a, float b)
{
    *reinterpret_cast<float2*>(p + idx) = make_float2(a, b);
}

__global__ __launch_bounds__(TPB, 2) void sim_kernel(
    const float* __restrict__ lamb,
    const float* __restrict__ mu,
    const float* __restrict__ buoy,
    const float* __restrict__ amps,   // [NSHOT, NSRC, NT]
    const int*   __restrict__ sloc,   // [NSHOT, NSRC, 2]
    const int*   __restrict__ rloc,   // [NSHOT, NREC, 2]
    float* __restrict__ out)          // [NSHOT, NREC, NT-1]
{
    // SMEM frames: stress over core+-6 (32x52), velocity over core+-4 (28x48)
    __shared__ float s_syy[32*SSP], s_sxy[32*SSP], s_sxx[32*SSP];
    __shared__ float s_vy [28*SVP], s_vx [28*SVP];

    const int tid  = threadIdx.x;
    const int blk  = blockIdx.x;
    const int shot = blk & 1;
    const int tile = blk >> 1;
    const int by0 = (tile / TCB) * TILE_R;
    const int bx0 = (tile % TCB) * TILE_C;
    const int rr = tid / 20;             // 0..19 core row
    const int pp = tid - rr * 20;        // 0..19 core pair
    const int y  = by0 + rr;
    const int x0 = bx0 + 2 * pp;
    const int base = shot * NS1;
    const int o = y * NG + x0;
    unsigned ph = g_phase;
    const unsigned F = g_flag[blk * 32];

    // 8 same-shot torus neighbors
    int nbid = 0;
    if (tid < 8) {
        const int dR[8] = {-1,-1,-1, 0, 0, 1, 1, 1};
        const int dC[8] = {-1, 0, 1,-1, 1,-1, 0, 1};
        int bR = tile / TCB, bC = tile % TCB;
        int nR = (bR + dR[tid] + TRB) % TRB;
        int nC = (bC + dC[tid] + TCB) % TCB;
        nbid = ((nR * TCB + nC) << 1) | shot;
    }

    // ---- core cell properties ----
    const float byv  = pml_b(y);
    const float bxv0 = pml_b(x0);
    const float bxv1 = pml_b(x0 + 1);
    const float2 bv2  = *reinterpret_cast<const float2*>(buoy + o);
    const float2 lam2 = *reinterpret_cast<const float2*>(lamb + o);
    const float2 mu2  = *reinterpret_cast<const float2*>(mu + o);
    const bool ybord = (y < 2 || y >= NG - 2);
    const float mk0 = (ybord || x0     < 2 || x0     >= NG - 2) ? 0.0f : 1.0f;
    const float mk1 = (ybord || x0 + 1 < 2 || x0 + 1 >= NG - 2) ? 0.0f : 1.0f;
    const int ssc = (rr + 6) * SSP + (x0 - bx0 + 6);   // core cell0 stress SMEM idx
    const int vvc = (rr + 4) * SVP + (x0 - bx0 + 4);   // core cell0 vel SMEM idx
    // skip global STG for inner core (never read by any neighbor)
    const bool do_stg = !(rr >= 6 && rr <= 13 && pp >= 3 && pp <= 16);

    unsigned smask = 0u;
#pragma unroll
    for (int s = 0; s < NSRC; s++) {
        int sy = sloc[(shot*NSRC + s)*2], sx = sloc[(shot*NSRC + s)*2 + 1];
        if (sy == y && sx == x0)     smask |= 1u << s;
        if (sy == y && sx == x0 + 1) smask |= 1u << (s + 8);
    }

    int rcode[8];
    int rcnt = 0;
    bool rovf = false;
    for (int r = 0; r < NREC; r++) {
        int e = shot * NREC + r;
        int ry = rloc[e*2], rx = rloc[e*2 + 1];
        if (ry == y && (rx == x0 || rx == x0 + 1)) {
            if (rcnt < 8) rcode[rcnt++] = e * 2 + (rx - x0);
            else rovf = true;
        }
    }

    // ---- velocity ring cells: annulus 1..4 (28x48 minus 20x40) = 544 cells ----
    // thread handles cell tid, plus tid+400 if tid<144
    int   rv_ss[2], rv_vv[2];
    float rv_byv[2], rv_bxv[2], rv_bv[2], rv_mk[2];
    unsigned rv_smask[2] = {0u, 0u};
    const int nrv = (tid < 144) ? 2 : 1;
#pragma unroll
    for (int i = 0; i < 2; i++) {
        int k = tid + i * 400;
        if (i == 1 && tid >= 144) break;
        int ey, ex;
        if (k < 192)      { ey = k / 48;              ex = k % 48; }
        else if (k < 384) { ey = 24 + (k - 192) / 48; ex = (k - 192) % 48; }
        else if (k < 464) { int j = k - 384; ey = 4 + j / 4; ex = j % 4; }
        else              { int j = k - 464; ey = 4 + j / 4; ex = 44 + j % 4; }
        int gy = (by0 + ey - 4 + NG) % NG;
        int gx = (bx0 + ex - 4 + NG) % NG;
        rv_ss[i] = (ey + 2) * SSP + (ex + 2);
        rv_vv[i] = ey * SVP + ex;
        rv_byv[i] = pml_b(gy);
        rv_bxv[i] = pml_b(gx);
        rv_bv[i]  = buoy[gy * NG + gx];
        rv_mk[i]  = (gy < 2 || gy >= NG-2 || gx < 2 || gx >= NG-2) ? 0.0f : 1.0f;
#pragma unroll
        for (int s = 0; s < NSRC; s++)
            if (sloc[(shot*NSRC + s)*2] == gy && sloc[(shot*NSRC + s)*2 + 1] == gx)
                rv_smask[i] |= 1u << s;
    }

    // ---- stress ring cells: annulus 1..2 (24x44 minus 20x40) = 256 cells ----
    const bool has_rs = (tid < 256);
    int   rs_ss = 0, rs_vv = 0;
    float rs_byv = 0, rs_bxv = 0, rs_lam = 0, rs_mu = 0, rs_mk = 0;
    if (has_rs) {
        int k = tid, ey2, ex2;
        if (k < 88)       { ey2 = k / 44;             ex2 = k % 44; }
        else if (k < 176) { ey2 = 22 + (k - 88) / 44; ex2 = (k - 88) % 44; }
        else if (k < 216) { int j = k - 176; ey2 = 2 + j / 2; ex2 = j % 2; }
        else              { int j = k - 216; ey2 = 2 + j / 2; ex2 = 42 + j % 2; }
        int gy = (by0 + ey2 - 2 + NG) % NG;
        int gx = (bx0 + ex2 - 2 + NG) % NG;
        rs_ss = (ey2 + 4) * SSP + (ex2 + 4);
        rs_vv = (ey2 + 2) * SVP + (ex2 + 2);
        rs_byv = pml_b(gy);
        rs_bxv = pml_b(gx);
        rs_lam = lamb[gy * NG + gx];
        rs_mu  = mu[gy * NG + gx];
        rs_mk  = (gy < 2 || gy >= NG-2 || gx < 2 || gx >= NG-2) ? 0.0f : 1.0f;
    }

    // ---- halo annulus 3..6 (32x52 minus 24x44) = 608 cells ----
    int h_s[2] = {0, 0}, h_g[2] = {0, 0};
    const int nh = (tid < 208) ? 2 : 1;
#pragma unroll
    for (int i = 0; i < 2; i++) {
        int k = tid + i * 400;
        if (i == 1 && tid >= 208) break;
        int ey3, ex3;
        if (k < 208)      { ey3 = k / 52;              ex3 = k % 52; }
        else if (k < 416) { ey3 = 28 + (k - 208) / 52; ex3 = (k - 208) % 52; }
        else if (k < 512) { int j = k - 416; ey3 = 4 + j / 4; ex3 = j % 4; }
        else              { int j = k - 512; ey3 = 4 + j / 4; ex3 = 48 + j % 4; }
        int gy = (by0 + ey3 - 6 + NG) % NG;
        int gx = (bx0 + ex3 - 6 + NG) % NG;
        h_s[i] = ey3 * SSP + ex3;
        h_g[i] = base + gy * NG + gx;
    }

    // ---- persistent CPML memory vars (registers) ----
    float cm_syyy[2] = {0,0}, cm_sxyx[2] = {0,0}, cm_sxxx[2] = {0,0}, cm_sxyy[2] = {0,0};
    float cm_vyy[2]  = {0,0}, cm_vxx[2]  = {0,0}, cm_vyx[2]  = {0,0}, cm_vxy[2]  = {0,0};
    float rvm_syyy[2] = {0,0}, rvm_sxyx[2] = {0,0}, rvm_sxxx[2] = {0,0}, rvm_sxyy[2] = {0,0};
    float rsm_vyy = 0, rsm_vxx = 0, rsm_vyx = 0, rsm_vxy = 0;

    // ---- init: zero SMEM frames + global stress buffer 2 core ----
    for (int i = tid; i < 32*SSP; i += TPB) { s_syy[i] = 0.f; s_sxy[i] = 0.f; s_sxx[i] = 0.f; }
    for (int i = tid; i < 28*SVP; i += TPB) { s_vy[i] = 0.f; s_vx[i] = 0.f; }
    st2(g_syy[2], base + o, 0.f, 0.f);
    st2(g_sxy[2], base + o, 0.f, 0.f);
    st2(g_sxx[2], base + o, 0.f, 0.f);
    __syncthreads();
    if (tid == 0) { __threadfence(); red_add(&g_flag[blk * 32]); }   // flag = F+1

    const float C1 = 1.125f;
    const float C2 = -1.0f / 24.0f;

    // velocity cell update (stress taps from SMEM; vy/vx persistent in SMEM)
    auto vel_cell = [&](int ss, int vv, float byv_, float bxv_, float bv_, float mk_,
                        float src, float& msyyy_, float& msxyx_, float& msxxx_, float& msxyy_)
    {
        float d, m;
        d = (C1*(s_syy[ss] - s_syy[ss-SSP]) + C2*(s_syy[ss+SSP] - s_syy[ss-2*SSP])) * IDHF;
        m = msyyy_; m = byv_*m + (byv_-1.0f)*d; msyyy_ = m;
        float ay = d + m;
        d = (C1*(s_sxy[ss+1] - s_sxy[ss]) + C2*(s_sxy[ss+2] - s_sxy[ss-1])) * IDHF;
        m = msxyx_; m = bxv_*m + (bxv_-1.0f)*d; msxyx_ = m;
        ay += d + m;
        float nvy = s_vy[vv] + DTF * bv_ * ay;
        d = (C1*(s_sxx[ss] - s_sxx[ss-1]) + C2*(s_sxx[ss+1] - s_sxx[ss-2])) * IDHF;
        m = msxxx_; m = bxv_*m + (bxv_-1.0f)*d; msxxx_ = m;
        float ax = d + m;
        d = (C1*(s_sxy[ss+SSP] - s_sxy[ss]) + C2*(s_sxy[ss+2*SSP] - s_sxy[ss-SSP])) * IDHF;
        m = msxyy_; m = byv_*m + (byv_-1.0f)*d; msxyy_ = m;
        ax += d + m;
        float nvx = (s_vx[vv] + DTF * bv_ * ax) * mk_;
        nvy = (nvy + src) * mk_;
        s_vy[vv] = nvy;
        s_vx[vv] = nvx;
    };

    // stress cell update (velocity taps from SMEM; stress persistent in SMEM)
    auto str_cell = [&](int ss, int vv, float byv_, float bxv_, float lam_, float mu_,
                        float mk_, float& mvyy_, float& mvxx_, float& mvyx_, float& mvxy_,
                        float& osyy, float& osxy, float& osxx)
    {
        float l2m_ = lam_ + 2.0f * mu_;
        float d, m;
        d = (C1*(s_vy[vv+SVP] - s_vy[vv]) + C2*(s_vy[vv+2*SVP] - s_vy[vv-SVP])) * IDHF;
        m = mvyy_; m = byv_*m + (byv_-1.0f)*d; mvyy_ = m;
        float e1 = d + m;
        d = (C1*(s_vx[vv] - s_vx[vv-1]) + C2*(s_vx[vv+1] - s_vx[vv-2])) * IDHF;
        m = mvxx_; m = bxv_*m + (bxv_-1.0f)*d; mvxx_ = m;
        float e2 = d + m;
        float nsyy = (s_syy[ss] + DTF*(l2m_*e1 + lam_*e2)) * mk_;
        float nsxx = (s_sxx[ss] + DTF*(l2m_*e2 + lam_*e1)) * mk_;
        d = (C1*(s_vy[vv+1] - s_vy[vv]) + C2*(s_vy[vv+2] - s_vy[vv-1])) * IDHF;
        m = mvyx_; m = bxv_*m + (bxv_-1.0f)*d; mvyx_ = m;
        float g = d + m;
        d = (C1*(s_vx[vv] - s_vx[vv-SVP]) + C2*(s_vx[vv+SVP] - s_vx[vv-2*SVP])) * IDHF;
        m = mvxy_; m = byv_*m + (byv_-1.0f)*d; mvxy_ = m;
        g += d + m;
        float nsxy = (s_sxy[ss] + DTF * mu_ * g) * mk_;
        s_syy[ss] = nsyy; s_sxy[ss] = nsxy; s_sxx[ss] = nsxx;
        osyy = nsyy; osxy = nsxy; osxx = nsxx;
    };

#pragma unroll 1
    for (int t = 0; t < NT; t++) {
        // wait: 8 same-shot neighbors completed step t-1
        if (tid < 8) {
            const unsigned tgt = F + 1u + (unsigned)t;
            const unsigned* fp = &g_flag[nbid * 32];
            while ((int)(ld_acq(fp) - tgt) < 0) { }
        }
        __syncthreads();

        const int p = (t + 2) % 3;
        const int q = t % 3;

        // ---- halo prefetch: annulus 3..6 of stress(t-1) from neighbors ----
        {
            const float* __restrict__ Syy = g_syy[p];
            const float* __restrict__ Sxy = g_sxy[p];
            const float* __restrict__ Sxx = g_sxx[p];
#pragma unroll
            for (int i = 0; i < 2; i++) {
                if (i < nh) {
                    int hs = h_s[i], hg = h_g[i];
                    s_syy[hs] = Syy[hg];
                    s_sxy[hs] = Sxy[hg];
                    s_sxx[hs] = Sxx[hg];
                }
            }
        }
        __syncthreads();

        // ---- velocity phase: core pair + ring cells, all from SMEM ----
        {
            float src0 = 0.f, src1 = 0.f;
            if (smask) {
#pragma unroll
                for (int s = 0; s < NSRC; s++) {
                    float a = amps[(shot*NSRC + s)*NT + t];
                    if (smask & (1u << s))       src0 += a;
                    if (smask & (1u << (s + 8))) src1 += a;
                }
                src0 *= DTF * bv2.x;
                src1 *= DTF * bv2.y;
            }
            vel_cell(ssc,     vvc,     byv, bxv0, bv2.x, mk0, src0,
                     cm_syyy[0], cm_sxyx[0], cm_sxxx[0], cm_sxyy[0]);
            vel_cell(ssc + 1, vvc + 1, byv, bxv1, bv2.y, mk1, src1,
                     cm_syyy[1], cm_sxyx[1], cm_sxxx[1], cm_sxyy[1]);
#pragma unroll
            for (int i = 0; i < 2; i++) {
                if (i < nrv) {
                    float src = 0.f;
                    if (rv_smask[i]) {
#pragma unroll
                        for (int s = 0; s < NSRC; s++)
                            if (rv_smask[i] & (1u << s))
                                src += amps[(shot*NSRC + s)*NT + t];
                        src *= DTF * rv_bv[i];
                    }
                    vel_cell(rv_ss[i], rv_vv[i], rv_byv[i], rv_bxv[i], rv_bv[i], rv_mk[i],
                             src, rvm_syyy[i], rvm_sxyx[i], rvm_sxxx[i], rvm_sxyy[i]);
                }
            }
        }
        __syncthreads();

        // receivers (vy from SMEM; no cross-block read)
        if (rovf) {
            for (int r = 0; r < NREC; r++) {
                int e = shot * NREC + r;
                int ry = rloc[e*2], rx = rloc[e*2 + 1];
                if (ry == y && (rx == x0 || rx == x0 + 1))
                    g_recs[t*(NSHOT*NREC) + e] = s_vy[vvc + (rx - x0)];
            }
        } else {
            for (int i = 0; i < rcnt; i++) {
                int e = rcode[i] >> 1, c = rcode[i] & 1;
                g_recs[t*(NSHOT*NREC) + e] = s_vy[vvc + c];
            }
        }

        // ---- stress phase: core pair (+STG outer frame) + ring cell ----
        {
            float y0, xy0, xx0, y1, xy1, xx1, dy, dxy, dxx;
            str_cell(ssc,     vvc,     byv, bxv0, lam2.x, mu2.x, mk0,
                     cm_vyy[0], cm_vxx[0], cm_vyx[0], cm_vxy[0], y0, xy0, xx0);
            str_cell(ssc + 1, vvc + 1, byv, bxv1, lam2.y, mu2.y, mk1,
                     cm_vyy[1], cm_vxx[1], cm_vyx[1], cm_vxy[1], y1, xy1, xx1);
            if (do_stg) {
                st2(g_syy[q], base + o, y0, y1);
                st2(g_sxy[q], base + o, xy0, xy1);
                st2(g_sxx[q], base + o, xx0, xx1);
            }
            if (has_rs) {
                str_cell(rs_ss, rs_vv, rs_byv, rs_bxv, rs_lam, rs_mu, rs_mk,
                         rsm_vyy, rsm_vxx, rsm_vyx, rsm_vxy, dy, dxy, dxx);
            }
        }

        // publish step t
        __syncthreads();
        if (tid == 0) { __threadfence(); red_add(&g_flag[blk * 32]); }
    }

    // ---------------- finalize ----------------
    gbar(ph + 1);
    const int gtid = blk * TPB + tid;
    const int total = NSHOT * NREC * (NT - 1);
    if (gtid < total) {
        int t = gtid % (NT - 1);
        int e = gtid / (NT - 1);
        out[e * (NT - 1) + t] = 0.5f * (g_recs[(t + 1)*(NSHOT*NREC) + e]
                                      + g_recs[t      *(NSHOT*NREC) + e]);
    }
}

extern "C" void kernel_launch(void* const* d_in, const int* in_sizes, int n_in,
                              void* d_out, int out_size)
{
    const float* lamb = (const float*)d_in[0];
    const float* mu   = (const float*)d_in[1];
    const float* buoy = (const float*)d_in[2];
    const float* amps = (const float*)d_in[3];
    const int*   sloc = (const int*)d_in[4];
    const int*   rloc = (const int*)d_in[5];
    float* out = (float*)d_out;

    sim_kernel<<<NBLK, TPB>>>(lamb, mu, buoy, amps, sloc, rloc, out);
}